// round 11
// baseline (speedup 1.0000x reference)
#include <cuda_runtime.h>
#include <cuda_bf16.h>
#include <stdint.h>
#include <math.h>

#define MAXN 40000
#define MAXE 640000

// ---------------- static device scratch ----------------
__device__ float g_q[MAXN * 128];
__device__ __nv_bfloat16 g_kbf[MAXN * 128];
__device__ __nv_bfloat16 g_vbf[MAXN * 128];
__device__ float g_rst[MAXN * 128];
__device__ __nv_bfloat16 g_rstbf[MAXN * 128];
__device__ float g_ffn[MAXN * 128];
__device__ __nv_bfloat16 g_hbf[MAXN * 512];
__device__ __nv_bfloat16 g_featbf[MAXN * 128];
__device__ __nv_bfloat16 g_WqT[128 * 128];
__device__ __nv_bfloat16 g_WkT[128 * 128];
__device__ __nv_bfloat16 g_WvT[128 * 128];
__device__ __nv_bfloat16 g_W1T[512 * 128];   // [n][k]
__device__ __nv_bfloat16 g_W2T[128 * 512];   // [n][k]
__device__ int g_deg[MAXN];
__device__ int g_cursor[MAXN];
__device__ int g_rowptr[MAXN + 1];
__device__ int g_esrc[MAXE];
__device__ int g_part[512];

// ---------------- prep: feat convert + weight transpose/convert + degree histogram ----------------
__global__ void k_prep(const float* __restrict__ feat,
                       const int* __restrict__ dst,
                       const float* __restrict__ Wq, const float* __restrict__ Wk,
                       const float* __restrict__ Wv, const float* __restrict__ W1,
                       const float* __restrict__ W2,
                       int nfeat4, int E) {
    int stride = gridDim.x * blockDim.x;
    int t0 = blockIdx.x * blockDim.x + threadIdx.x;

    // feat -> bf16 (vectorized by 4)
    for (int i = t0; i < nfeat4; i += stride) {
        int j = i * 4;
        float4 v = *reinterpret_cast<const float4*>(feat + j);
        __nv_bfloat162 a, b;
        a.x = __float2bfloat16_rn(v.x); a.y = __float2bfloat16_rn(v.y);
        b.x = __float2bfloat16_rn(v.z); b.y = __float2bfloat16_rn(v.w);
        *reinterpret_cast<__nv_bfloat162*>(&g_featbf[j]) = a;
        *reinterpret_cast<__nv_bfloat162*>(&g_featbf[j + 2]) = b;
    }

    // degree histogram
    for (int e = t0; e < E; e += stride) atomicAdd(&g_deg[dst[e]], 1);

    // weight transpose+convert: [Kd][Nd] f32 -> [Nd][Kd] bf16
    for (int i = t0; i < 128 * 128; i += stride) {
        int nn = i >> 7, kk = i & 127;
        g_WqT[i] = __float2bfloat16_rn(Wq[kk * 128 + nn]);
        g_WkT[i] = __float2bfloat16_rn(Wk[kk * 128 + nn]);
        g_WvT[i] = __float2bfloat16_rn(Wv[kk * 128 + nn]);
    }
    for (int i = t0; i < 512 * 128; i += stride) {
        int nn = i >> 7, kk = i & 127;          // W1T[n][k], n<512, k<128
        g_W1T[i] = __float2bfloat16_rn(W1[kk * 512 + nn]);
        int n2 = i >> 9, k2 = i & 511;          // W2T[n][k], n<128, k<512
        g_W2T[i] = __float2bfloat16_rn(W2[k2 * 128 + n2]);
    }
}

// ---------------- CSR scan ----------------
__global__ void k_scan1(int n) {
    __shared__ int sh[256];
    int b = blockIdx.x, t = threadIdx.x;
    int i = b * 256 + t;
    int v = (i < n) ? g_deg[i] : 0;
    sh[t] = v; __syncthreads();
    for (int off = 1; off < 256; off <<= 1) {
        int x = (t >= off) ? sh[t - off] : 0; __syncthreads();
        sh[t] += x; __syncthreads();
    }
    if (i < n) g_rowptr[i + 1] = sh[t];
    if (t == 255) g_part[b] = sh[255];
    if (b == 0 && t == 0) g_rowptr[0] = 0;
}

__global__ void k_scan2(int nb) {
    __shared__ int sh[256];
    int t = threadIdx.x;
    int v = (t < nb) ? g_part[t] : 0;
    sh[t] = v; __syncthreads();
    for (int off = 1; off < 256; off <<= 1) {
        int x = (t >= off) ? sh[t - off] : 0; __syncthreads();
        sh[t] += x; __syncthreads();
    }
    if (t < nb) g_part[t] = sh[t] - v;  // exclusive
}

__global__ void k_scan3(int n) {
    int i = blockIdx.x * blockDim.x + threadIdx.x;
    if (i < n) g_rowptr[i + 1] += g_part[i >> 8];
}

// ---------------- bf16 tensor-core GEMM ----------------
#define ASTRIDE 20  // u32 per smem row: 16 used + 4 pad (conflict-free fragment LDS)

__device__ __forceinline__ void mma_bf16(float* c, const unsigned* a, const unsigned* b) {
    asm volatile(
        "mma.sync.aligned.m16n8k16.row.col.f32.bf16.bf16.f32 "
        "{%0,%1,%2,%3}, {%4,%5,%6,%7}, {%8,%9}, {%0,%1,%2,%3};\n"
        : "+f"(c[0]), "+f"(c[1]), "+f"(c[2]), "+f"(c[3])
        : "r"(a[0]), "r"(a[1]), "r"(a[2]), "r"(a[3]), "r"(b[0]), "r"(b[1]));
}

__device__ __forceinline__ void cp16(unsigned int dsh, const void* src, int nbytes) {
    asm volatile("cp.async.cg.shared.global [%0], [%1], 16, %2;\n"
                 :: "r"(dsh), "l"(src), "r"(nbytes));
}

// BM=128 BN=128 BK=32, 256 threads, cp.async double-buffered.
__device__ __forceinline__ void gemm_core(
    const __nv_bfloat16* __restrict__ A, const __nv_bfloat16* __restrict__ BT,
    int M, int Kd, int Ncol, int row0, int col0,
    float* __restrict__ Cf, __nv_bfloat16* __restrict__ Cb,
    const float* __restrict__ bias, const float* __restrict__ prelu)
{
    __shared__ unsigned As[2][128 * ASTRIDE];
    __shared__ unsigned Bs[2][128 * ASTRIDE];

    int tid = threadIdx.x, lane = tid & 31, warp = tid >> 5;
    int wm = warp & 1, wn = warp >> 1;
    int g = lane >> 2, tg = lane & 3;

    float acc[4][4][4];
#pragma unroll
    for (int mt = 0; mt < 4; mt++)
#pragma unroll
        for (int nt = 0; nt < 4; nt++)
#pragma unroll
            for (int r = 0; r < 4; r++) acc[mt][nt][r] = 0.f;

    int lrow = tid >> 2;
    int lq = tid & 3;
    unsigned int saA0 = (unsigned int)__cvta_generic_to_shared(&As[0][0]);
    unsigned int saB0 = (unsigned int)__cvta_generic_to_shared(&Bs[0][0]);

    int KT = Kd >> 5;

    auto issue = [&](int s, int k0) {
        unsigned int baseA = saA0 + (unsigned int)s * 128 * ASTRIDE * 4;
        unsigned int baseB = saB0 + (unsigned int)s * 128 * ASTRIDE * 4;
#pragma unroll
        for (int r = 0; r < 2; r++) {
            int row = lrow + r * 64;
            unsigned int doff = (unsigned int)(row * ASTRIDE + lq * 4) * 4;
            const __nv_bfloat16* sA = A + (long)(row0 + row) * Kd + k0 + lq * 8;
            cp16(baseA + doff, sA, (row0 + row < M) ? 16 : 0);
            const __nv_bfloat16* sB = BT + (long)(col0 + row) * Kd + k0 + lq * 8;
            cp16(baseB + doff, sB, 16);
        }
        asm volatile("cp.async.commit_group;\n");
    };

    issue(0, 0);
    for (int kt = 0; kt < KT; kt++) {
        int cur = kt & 1;
        if (kt + 1 < KT) {
            issue(cur ^ 1, (kt + 1) * 32);
            asm volatile("cp.async.wait_group 1;\n");
        } else {
            asm volatile("cp.async.wait_group 0;\n");
        }
        __syncthreads();

        const unsigned* Ac = As[cur];
        const unsigned* Bc = Bs[cur];
#pragma unroll
        for (int kb = 0; kb < 2; kb++) {
            int kk2 = kb * 8;
            unsigned af[4][4];
#pragma unroll
            for (int mt = 0; mt < 4; mt++) {
                int mr = (wm * 64 + mt * 16 + g) * ASTRIDE;
                af[mt][0] = Ac[mr + kk2 + tg];
                af[mt][1] = Ac[mr + 8 * ASTRIDE + kk2 + tg];
                af[mt][2] = Ac[mr + kk2 + tg + 4];
                af[mt][3] = Ac[mr + 8 * ASTRIDE + kk2 + tg + 4];
            }
            unsigned bf[4][2];
#pragma unroll
            for (int nt = 0; nt < 4; nt++) {
                int nr = (wn * 32 + nt * 8 + g) * ASTRIDE;
                bf[nt][0] = Bc[nr + kk2 + tg];
                bf[nt][1] = Bc[nr + kk2 + tg + 4];
            }
#pragma unroll
            for (int mt = 0; mt < 4; mt++)
#pragma unroll
                for (int nt = 0; nt < 4; nt++)
                    mma_bf16(acc[mt][nt], af[mt], bf[nt]);
        }
        __syncthreads();
    }

    // epilogue
#pragma unroll
    for (int mt = 0; mt < 4; mt++) {
        int rbase = row0 + wm * 64 + mt * 16 + g;
#pragma unroll
        for (int nt = 0; nt < 4; nt++) {
            int c = col0 + wn * 32 + nt * 8 + 2 * tg;
#pragma unroll
            for (int half = 0; half < 2; half++) {
                int r = rbase + half * 8;
                if (r >= M) continue;
                float v0 = acc[mt][nt][half * 2 + 0];
                float v1 = acc[mt][nt][half * 2 + 1];
                if (bias) { v0 += bias[c]; v1 += bias[c + 1]; }
                if (prelu) {
                    v0 = (v0 >= 0.f) ? v0 : prelu[c] * v0;
                    v1 = (v1 >= 0.f) ? v1 : prelu[c + 1] * v1;
                }
                if (Cf) {
                    float2 o = make_float2(v0, v1);
                    *reinterpret_cast<float2*>(&Cf[(long)r * Ncol + c]) = o;
                } else {
                    __nv_bfloat162 o;
                    o.x = __float2bfloat16_rn(v0);
                    o.y = __float2bfloat16_rn(v1);
                    *reinterpret_cast<__nv_bfloat162*>(&Cb[(long)r * Ncol + c]) = o;
                }
            }
        }
    }
}

// QKV + fused CSR fill (fill runs before the GEMM body; attn consumes it later)
__global__ __launch_bounds__(256) void gemm_qkv(int M, const int* __restrict__ dst,
                                                const int* __restrict__ src, int E) {
    int stride = gridDim.x * gridDim.y * blockDim.x;
    int t0 = (blockIdx.y * gridDim.x + blockIdx.x) * blockDim.x + threadIdx.x;
    for (int e = t0; e < E; e += stride) {
        int d = dst[e];
        int pos = atomicAdd(&g_cursor[d], 1);
        g_esrc[g_rowptr[d] + pos] = src[e];
    }

    int which = blockIdx.x;
    const __nv_bfloat16* BT = (which == 0) ? g_WqT : (which == 1) ? g_WkT : g_WvT;
    float* Cf = (which == 0) ? g_q : nullptr;
    __nv_bfloat16* Cb = (which == 1) ? g_kbf : (which == 2) ? g_vbf : nullptr;
    gemm_core(g_featbf, BT, M, 128, 128, blockIdx.y * 128, 0, Cf, Cb, nullptr, nullptr);
}

__global__ __launch_bounds__(256) void gemm_ffn1(int M, const float* __restrict__ b1,
                                                 const float* __restrict__ prelu) {
    gemm_core(g_rstbf, g_W1T, M, 128, 512, blockIdx.y * 128, blockIdx.x * 128,
              nullptr, g_hbf, b1, prelu);
}

__global__ __launch_bounds__(256) void gemm_ffn2(int M, const float* __restrict__ b2) {
    gemm_core(g_hbf, g_W2T, M, 512, 128, blockIdx.y * 128, 0, g_ffn, nullptr, b2, nullptr);
}

// ---------------- attention: warp per node, online softmax, register-resident ----------------
__global__ __launch_bounds__(256) void k_attn(
    const float* __restrict__ feat,
    const float* __restrict__ ln1g, const float* __restrict__ ln1b, int N)
{
    int gw = (blockIdx.x * blockDim.x + threadIdx.x) >> 5;
    if (gw >= N) return;
    int lane = threadIdx.x & 31;
    int node = gw;

    int rs = g_rowptr[node], re = g_rowptr[node + 1];

    // lane l owns channels 4l..4l+3 (head = l>>2)
    float4 q4 = *reinterpret_cast<const float4*>(&g_q[(long)node * 128 + lane * 4]);
    const float scale = 0.08838834764831845f;  // 1/sqrt(128)
    q4.x *= scale; q4.y *= scale; q4.z *= scale; q4.w *= scale;

    float m = -INFINITY, ssum = 0.f;
    float a0 = 0.f, a1 = 0.f, a2 = 0.f, a3 = 0.f;

    for (int base = rs; base < re; base += 32) {
        int nchunk = min(32, re - base);
        int sreg = (base + lane < re) ? g_esrc[base + lane] : 0;
        for (int j = 0; j < nchunk; j++) {
            int s = __shfl_sync(0xffffffffu, sreg, j);
            uint2 u = *reinterpret_cast<const uint2*>(&g_kbf[(long)s * 128 + lane * 4]);
            uint2 uv = *reinterpret_cast<const uint2*>(&g_vbf[(long)s * 128 + lane * 4]);
            __nv_bfloat162 b0 = *reinterpret_cast<__nv_bfloat162*>(&u.x);
            __nv_bfloat162 b1 = *reinterpret_cast<__nv_bfloat162*>(&u.y);
            float2 f0 = __bfloat1622float2(b0), f1 = __bfloat1622float2(b1);
            float p = f0.x * q4.x + f0.y * q4.y + f1.x * q4.z + f1.y * q4.w;
            p += __shfl_xor_sync(0xffffffffu, p, 1);
            p += __shfl_xor_sync(0xffffffffu, p, 2);

            __nv_bfloat162 vb0 = *reinterpret_cast<__nv_bfloat162*>(&uv.x);
            __nv_bfloat162 vb1 = *reinterpret_cast<__nv_bfloat162*>(&uv.y);
            float2 v0 = __bfloat1622float2(vb0), v1 = __bfloat1622float2(vb1);

            float mn = fmaxf(m, p);
            float c = __expf(m - mn);   // first edge: exp(-inf)=0
            float w = __expf(p - mn);
            ssum = ssum * c + w;
            a0 = a0 * c + w * v0.x;
            a1 = a1 * c + w * v0.y;
            a2 = a2 * c + w * v1.x;
            a3 = a3 * c + w * v1.y;
            m = mn;
        }
    }

    float inv = (ssum > 0.f) ? (1.f / ssum) : 0.f;
    float4 fr = *reinterpret_cast<const float4*>(&feat[(long)node * 128 + lane * 4]);
    float x0 = a0 * inv + fr.x;
    float x1 = a1 * inv + fr.y;
    float x2 = a2 * inv + fr.z;
    float x3 = a3 * inv + fr.w;

    float part = x0 + x1 + x2 + x3;
#pragma unroll
    for (int o = 16; o >= 1; o >>= 1) part += __shfl_xor_sync(0xffffffffu, part, o);
    float mu = part * (1.f / 128.f);
    float d0 = x0 - mu, d1 = x1 - mu, d2 = x2 - mu, d3 = x3 - mu;
    float vp = d0 * d0 + d1 * d1 + d2 * d2 + d3 * d3;
#pragma unroll
    for (int o = 16; o >= 1; o >>= 1) vp += __shfl_xor_sync(0xffffffffu, vp, o);
    float rstd = rsqrtf(vp * (1.f / 128.f) + 1e-5f);

    float4 gg = *reinterpret_cast<const float4*>(&ln1g[lane * 4]);
    float4 bb = *reinterpret_cast<const float4*>(&ln1b[lane * 4]);
    float y0 = d0 * rstd * gg.x + bb.x;
    float y1 = d1 * rstd * gg.y + bb.y;
    float y2 = d2 * rstd * gg.z + bb.z;
    float y3 = d3 * rstd * gg.w + bb.w;

    float4 o4 = make_float4(y0, y1, y2, y3);
    *reinterpret_cast<float4*>(&g_rst[(long)node * 128 + lane * 4]) = o4;
    __nv_bfloat162 p0, p1;
    p0.x = __float2bfloat16_rn(y0); p0.y = __float2bfloat16_rn(y1);
    p1.x = __float2bfloat16_rn(y2); p1.y = __float2bfloat16_rn(y3);
    uint2 pk;
    pk.x = *reinterpret_cast<unsigned*>(&p0);
    pk.y = *reinterpret_cast<unsigned*>(&p1);
    *reinterpret_cast<uint2*>(&g_rstbf[(long)node * 128 + lane * 4]) = pk;
}

// ---------------- residual + LayerNorm2 -> output (warp per node) ----------------
__global__ __launch_bounds__(256) void k_ln2(
    const float* __restrict__ ln2g, const float* __restrict__ ln2b,
    float* __restrict__ out, int N)
{
    int gw = (blockIdx.x * blockDim.x + threadIdx.x) >> 5;
    if (gw >= N) return;
    int lane = threadIdx.x & 31;

    float4 r4 = *reinterpret_cast<const float4*>(&g_rst[(long)gw * 128 + lane * 4]);
    float4 f4 = *reinterpret_cast<const float4*>(&g_ffn[(long)gw * 128 + lane * 4]);
    float x0 = r4.x + f4.x, x1 = r4.y + f4.y, x2 = r4.z + f4.z, x3 = r4.w + f4.w;

    float part = x0 + x1 + x2 + x3;
#pragma unroll
    for (int o = 16; o >= 1; o >>= 1) part += __shfl_xor_sync(0xffffffffu, part, o);
    float mu = part * (1.f / 128.f);
    float d0 = x0 - mu, d1 = x1 - mu, d2 = x2 - mu, d3 = x3 - mu;
    float vp = d0 * d0 + d1 * d1 + d2 * d2 + d3 * d3;
#pragma unroll
    for (int o = 16; o >= 1; o >>= 1) vp += __shfl_xor_sync(0xffffffffu, vp, o);
    float rstd = rsqrtf(vp * (1.f / 128.f) + 1e-5f);

    float4 gg = *reinterpret_cast<const float4*>(&ln2g[lane * 4]);
    float4 bb = *reinterpret_cast<const float4*>(&ln2b[lane * 4]);
    float4 o4;
    o4.x = d0 * rstd * gg.x + bb.x;
    o4.y = d1 * rstd * gg.y + bb.y;
    o4.z = d2 * rstd * gg.z + bb.z;
    o4.w = d3 * rstd * gg.w + bb.w;
    *reinterpret_cast<float4*>(&out[(long)gw * 128 + lane * 4]) = o4;
}

// ---------------- launch ----------------
extern "C" void kernel_launch(void* const* d_in, const int* in_sizes, int n_in,
                              void* d_out, int out_size)
{
    const float* feat  = (const float*)d_in[0];
    const int*   src   = (const int*)d_in[1];
    const int*   dst   = (const int*)d_in[2];
    const float* Wq    = (const float*)d_in[3];
    const float* Wk    = (const float*)d_in[4];
    const float* Wv    = (const float*)d_in[5];
    const float* ln1g  = (const float*)d_in[6];
    const float* ln1b  = (const float*)d_in[7];
    const float* ln2g  = (const float*)d_in[8];
    const float* ln2b  = (const float*)d_in[9];
    const float* W1    = (const float*)d_in[10];
    const float* b1    = (const float*)d_in[11];
    const float* prelu = (const float*)d_in[12];
    const float* W2    = (const float*)d_in[13];
    const float* b2    = (const float*)d_in[14];
    float* out = (float*)d_out;

    int N = in_sizes[0] / 128;
    int E = in_sizes[1];

    void *degp, *curp;
    cudaGetSymbolAddress(&degp, g_deg);
    cudaGetSymbolAddress(&curp, g_cursor);
    cudaMemsetAsync(degp, 0, (size_t)N * 4);
    cudaMemsetAsync(curp, 0, (size_t)N * 4);

    // prep: feat->bf16, weight transpose->bf16, degree histogram (one launch)
    k_prep<<<2368, 256>>>(feat, dst, Wq, Wk, Wv, W1, W2, N * 32, E);

    // CSR scan
    int nb = (N + 255) / 256;
    k_scan1<<<nb, 256>>>(N);
    k_scan2<<<1, 256>>>(nb);
    k_scan3<<<nb, 256>>>(N);

    int mblk = (N + 127) / 128;

    // QKV (bf16 tensor cores) + fused CSR fill
    dim3 gqkv(3, mblk);
    gemm_qkv<<<gqkv, 256>>>(N, dst, src, E);

    // attention + aggregate + residual + LN1 (warp per node)
    k_attn<<<(N * 32 + 255) / 256, 256>>>(feat, ln1g, ln1b, N);

    // FFN
    dim3 gff1(4, mblk);
    gemm_ffn1<<<gff1, 256>>>(N, b1, prelu);
    dim3 gff2(1, mblk);
    gemm_ffn2<<<gff2, 256>>>(N, b2);

    // residual + LN2 -> out (warp per node)
    k_ln2<<<(N * 32 + 255) / 256, 256>>>(ln2g, ln2b, out, N);
}

// round 12
// speedup vs baseline: 1.4067x; 1.4067x over previous
#include <cuda_runtime.h>
#include <cuda_bf16.h>
#include <stdint.h>
#include <math.h>

#define MAXN 40000
#define MAXE 640000

// ---------------- static device scratch ----------------
__device__ float g_q[MAXN * 128];
__device__ __nv_bfloat16 g_kbf[MAXN * 128];
__device__ __nv_bfloat16 g_vbf[MAXN * 128];
__device__ float g_rst[MAXN * 128];
__device__ __nv_bfloat16 g_rstbf[MAXN * 128];
__device__ float g_ffn[MAXN * 128];
__device__ __nv_bfloat16 g_hbf[MAXN * 512];
__device__ __nv_bfloat16 g_featbf[MAXN * 128];
__device__ __nv_bfloat16 g_WqT[128 * 128];
__device__ __nv_bfloat16 g_WkT[128 * 128];
__device__ __nv_bfloat16 g_WvT[128 * 128];
__device__ __nv_bfloat16 g_W1T[512 * 128];   // [n][k]
__device__ __nv_bfloat16 g_W2T[128 * 512];   // [n][k]
__device__ int g_deg[MAXN];
__device__ int g_cursor[MAXN];
__device__ int g_rowptr[MAXN + 1];
__device__ int g_esrc[MAXE];
__device__ int g_part[512];

// ---------------- converts ----------------
__global__ void k_cvt_feat(const float* __restrict__ f, int n) {
    int i = (blockIdx.x * blockDim.x + threadIdx.x) * 4;
    if (i < n) {
        float4 v = *reinterpret_cast<const float4*>(f + i);
        __nv_bfloat162 a, b;
        a.x = __float2bfloat16_rn(v.x); a.y = __float2bfloat16_rn(v.y);
        b.x = __float2bfloat16_rn(v.z); b.y = __float2bfloat16_rn(v.w);
        *reinterpret_cast<__nv_bfloat162*>(&g_featbf[i]) = a;
        *reinterpret_cast<__nv_bfloat162*>(&g_featbf[i + 2]) = b;
    }
}

// transpose+convert weights: in [Kd][Nd] f32 -> out [Nd][Kd] bf16
__global__ void k_cvt_w(const float* __restrict__ Wq, const float* __restrict__ Wk,
                        const float* __restrict__ Wv, const float* __restrict__ W1,
                        const float* __restrict__ W2) {
    int m = blockIdx.y;
    const float* src; __nv_bfloat16* dst; int Kd, Nd;
    if (m == 0) { src = Wq; dst = g_WqT; Kd = 128; Nd = 128; }
    else if (m == 1) { src = Wk; dst = g_WkT; Kd = 128; Nd = 128; }
    else if (m == 2) { src = Wv; dst = g_WvT; Kd = 128; Nd = 128; }
    else if (m == 3) { src = W1; dst = g_W1T; Kd = 128; Nd = 512; }
    else { src = W2; dst = g_W2T; Kd = 512; Nd = 128; }
    int tot = Kd * Nd;
    for (int i = blockIdx.x * blockDim.x + threadIdx.x; i < tot;
         i += gridDim.x * blockDim.x) {
        int nn = i / Kd, kk = i - nn * Kd;
        dst[i] = __float2bfloat16_rn(src[kk * Nd + nn]);
    }
}

// ---------------- CSR build ----------------
__global__ void k_hist(const int* __restrict__ dst, int E) {
    int e = blockIdx.x * blockDim.x + threadIdx.x;
    if (e < E) atomicAdd(&g_deg[dst[e]], 1);
}

__global__ void k_scan1(int n) {
    __shared__ int sh[256];
    int b = blockIdx.x, t = threadIdx.x;
    int i = b * 256 + t;
    int v = (i < n) ? g_deg[i] : 0;
    sh[t] = v; __syncthreads();
    for (int off = 1; off < 256; off <<= 1) {
        int x = (t >= off) ? sh[t - off] : 0; __syncthreads();
        sh[t] += x; __syncthreads();
    }
    if (i < n) g_rowptr[i + 1] = sh[t];
    if (t == 255) g_part[b] = sh[255];
    if (b == 0 && t == 0) g_rowptr[0] = 0;
}

__global__ void k_scan2(int nb) {
    __shared__ int sh[256];
    int t = threadIdx.x;
    int v = (t < nb) ? g_part[t] : 0;
    sh[t] = v; __syncthreads();
    for (int off = 1; off < 256; off <<= 1) {
        int x = (t >= off) ? sh[t - off] : 0; __syncthreads();
        sh[t] += x; __syncthreads();
    }
    if (t < nb) g_part[t] = sh[t] - v;  // exclusive
}

__global__ void k_scan3(int n) {
    int i = blockIdx.x * blockDim.x + threadIdx.x;
    if (i < n) g_rowptr[i + 1] += g_part[i >> 8];
}

__global__ void k_fill(const int* __restrict__ dst, const int* __restrict__ src, int E) {
    int e = blockIdx.x * blockDim.x + threadIdx.x;
    if (e < E) {
        int d = dst[e];
        int pos = atomicAdd(&g_cursor[d], 1);
        g_esrc[g_rowptr[d] + pos] = src[e];
    }
}

// ---------------- bf16 tensor-core GEMM ----------------
#define ASTRIDE 20  // u32 per smem row: 16 used + 4 pad (conflict-free fragment LDS)

__device__ __forceinline__ void mma_bf16(float* c, const unsigned* a, const unsigned* b) {
    asm volatile(
        "mma.sync.aligned.m16n8k16.row.col.f32.bf16.bf16.f32 "
        "{%0,%1,%2,%3}, {%4,%5,%6,%7}, {%8,%9}, {%0,%1,%2,%3};\n"
        : "+f"(c[0]), "+f"(c[1]), "+f"(c[2]), "+f"(c[3])
        : "r"(a[0]), "r"(a[1]), "r"(a[2]), "r"(a[3]), "r"(b[0]), "r"(b[1]));
}

__device__ __forceinline__ void cp16(unsigned int dsh, const void* src, int nbytes) {
    asm volatile("cp.async.cg.shared.global [%0], [%1], 16, %2;\n"
                 :: "r"(dsh), "l"(src), "r"(nbytes));
}

// BM=128 BN=128 BK=32, 256 threads, cp.async double-buffered.
// A: bf16 [M][Kd] row-major.  BT: bf16 [Ncol][Kd] row-major (pre-transposed).
__device__ __forceinline__ void gemm_core(
    const __nv_bfloat16* __restrict__ A, const __nv_bfloat16* __restrict__ BT,
    int M, int Kd, int Ncol, int row0, int col0,
    float* __restrict__ Cf, __nv_bfloat16* __restrict__ Cb,
    const float* __restrict__ bias, const float* __restrict__ prelu)
{
    __shared__ unsigned As[2][128 * ASTRIDE];
    __shared__ unsigned Bs[2][128 * ASTRIDE];

    int tid = threadIdx.x, lane = tid & 31, warp = tid >> 5;
    int wm = warp & 1, wn = warp >> 1;
    int g = lane >> 2, tg = lane & 3;

    float acc[4][4][4];
#pragma unroll
    for (int mt = 0; mt < 4; mt++)
#pragma unroll
        for (int nt = 0; nt < 4; nt++)
#pragma unroll
            for (int r = 0; r < 4; r++) acc[mt][nt][r] = 0.f;

    int lrow = tid >> 2;
    int lq = tid & 3;
    unsigned int saA0 = (unsigned int)__cvta_generic_to_shared(&As[0][0]);
    unsigned int saB0 = (unsigned int)__cvta_generic_to_shared(&Bs[0][0]);

    int KT = Kd >> 5;

    auto issue = [&](int s, int k0) {
        unsigned int baseA = saA0 + (unsigned int)s * 128 * ASTRIDE * 4;
        unsigned int baseB = saB0 + (unsigned int)s * 128 * ASTRIDE * 4;
#pragma unroll
        for (int r = 0; r < 2; r++) {
            int row = lrow + r * 64;
            unsigned int doff = (unsigned int)(row * ASTRIDE + lq * 4) * 4;
            const __nv_bfloat16* sA = A + (long)(row0 + row) * Kd + k0 + lq * 8;
            cp16(baseA + doff, sA, (row0 + row < M) ? 16 : 0);
            const __nv_bfloat16* sB = BT + (long)(col0 + row) * Kd + k0 + lq * 8;
            cp16(baseB + doff, sB, 16);
        }
        asm volatile("cp.async.commit_group;\n");
    };

    issue(0, 0);
    for (int kt = 0; kt < KT; kt++) {
        int cur = kt & 1;
        if (kt + 1 < KT) {
            issue(cur ^ 1, (kt + 1) * 32);
            asm volatile("cp.async.wait_group 1;\n");
        } else {
            asm volatile("cp.async.wait_group 0;\n");
        }
        __syncthreads();

        const unsigned* Ac = As[cur];
        const unsigned* Bc = Bs[cur];
#pragma unroll
        for (int kb = 0; kb < 2; kb++) {
            int kk2 = kb * 8;
            unsigned af[4][4];
#pragma unroll
            for (int mt = 0; mt < 4; mt++) {
                int mr = (wm * 64 + mt * 16 + g) * ASTRIDE;
                af[mt][0] = Ac[mr + kk2 + tg];
                af[mt][1] = Ac[mr + 8 * ASTRIDE + kk2 + tg];
                af[mt][2] = Ac[mr + kk2 + tg + 4];
                af[mt][3] = Ac[mr + 8 * ASTRIDE + kk2 + tg + 4];
            }
            unsigned bf[4][2];
#pragma unroll
            for (int nt = 0; nt < 4; nt++) {
                int nr = (wn * 32 + nt * 8 + g) * ASTRIDE;
                bf[nt][0] = Bc[nr + kk2 + tg];
                bf[nt][1] = Bc[nr + kk2 + tg + 4];
            }
#pragma unroll
            for (int mt = 0; mt < 4; mt++)
#pragma unroll
                for (int nt = 0; nt < 4; nt++)
                    mma_bf16(acc[mt][nt], af[mt], bf[nt]);
        }
        __syncthreads();
    }

    // epilogue
#pragma unroll
    for (int mt = 0; mt < 4; mt++) {
        int rbase = row0 + wm * 64 + mt * 16 + g;
#pragma unroll
        for (int nt = 0; nt < 4; nt++) {
            int c = col0 + wn * 32 + nt * 8 + 2 * tg;
#pragma unroll
            for (int half = 0; half < 2; half++) {
                int r = rbase + half * 8;
                if (r >= M) continue;
                float v0 = acc[mt][nt][half * 2 + 0];
                float v1 = acc[mt][nt][half * 2 + 1];
                if (bias) { v0 += bias[c]; v1 += bias[c + 1]; }
                if (prelu) {
                    v0 = (v0 >= 0.f) ? v0 : prelu[c] * v0;
                    v1 = (v1 >= 0.f) ? v1 : prelu[c + 1] * v1;
                }
                if (Cf) {
                    float2 o = make_float2(v0, v1);
                    *reinterpret_cast<float2*>(&Cf[(long)r * Ncol + c]) = o;
                } else {
                    __nv_bfloat162 o;
                    o.x = __float2bfloat16_rn(v0);
                    o.y = __float2bfloat16_rn(v1);
                    *reinterpret_cast<__nv_bfloat162*>(&Cb[(long)r * Ncol + c]) = o;
                }
            }
        }
    }
}

__global__ __launch_bounds__(256) void gemm_qkv(int M) {
    int which = blockIdx.x;
    const __nv_bfloat16* BT = (which == 0) ? g_WqT : (which == 1) ? g_WkT : g_WvT;
    float* Cf = (which == 0) ? g_q : nullptr;
    __nv_bfloat16* Cb = (which == 1) ? g_kbf : (which == 2) ? g_vbf : nullptr;
    gemm_core(g_featbf, BT, M, 128, 128, blockIdx.y * 128, 0, Cf, Cb, nullptr, nullptr);
}

__global__ __launch_bounds__(256) void gemm_ffn1(int M, const float* __restrict__ b1,
                                                 const float* __restrict__ prelu) {
    gemm_core(g_rstbf, g_W1T, M, 128, 512, blockIdx.y * 128, blockIdx.x * 128,
              nullptr, g_hbf, b1, prelu);
}

__global__ __launch_bounds__(256) void gemm_ffn2(int M, const float* __restrict__ b2) {
    gemm_core(g_hbf, g_W2T, M, 512, 128, blockIdx.y * 128, 0, g_ffn, nullptr, b2, nullptr);
}

// ---------------- attention: warp per node, online softmax, register-resident ----------------
__global__ __launch_bounds__(256) void k_attn(
    const float* __restrict__ feat,
    const float* __restrict__ ln1g, const float* __restrict__ ln1b, int N)
{
    int gw = (blockIdx.x * blockDim.x + threadIdx.x) >> 5;
    if (gw >= N) return;
    int lane = threadIdx.x & 31;
    int node = gw;

    int rs = g_rowptr[node], re = g_rowptr[node + 1];

    // lane l owns channels 4l..4l+3 (head = l>>2)
    float4 q4 = *reinterpret_cast<const float4*>(&g_q[(long)node * 128 + lane * 4]);
    const float scale = 0.08838834764831845f;  // 1/sqrt(128)
    q4.x *= scale; q4.y *= scale; q4.z *= scale; q4.w *= scale;

    float m = -INFINITY, ssum = 0.f;
    float a0 = 0.f, a1 = 0.f, a2 = 0.f, a3 = 0.f;

    for (int base = rs; base < re; base += 32) {
        int nchunk = min(32, re - base);
        int sreg = (base + lane < re) ? g_esrc[base + lane] : 0;
        for (int j = 0; j < nchunk; j++) {
            int s = __shfl_sync(0xffffffffu, sreg, j);
            uint2 u = *reinterpret_cast<const uint2*>(&g_kbf[(long)s * 128 + lane * 4]);
            uint2 uv = *reinterpret_cast<const uint2*>(&g_vbf[(long)s * 128 + lane * 4]);
            __nv_bfloat162 b0 = *reinterpret_cast<__nv_bfloat162*>(&u.x);
            __nv_bfloat162 b1 = *reinterpret_cast<__nv_bfloat162*>(&u.y);
            float2 f0 = __bfloat1622float2(b0), f1 = __bfloat1622float2(b1);
            float p = f0.x * q4.x + f0.y * q4.y + f1.x * q4.z + f1.y * q4.w;
            p += __shfl_xor_sync(0xffffffffu, p, 1);
            p += __shfl_xor_sync(0xffffffffu, p, 2);

            __nv_bfloat162 vb0 = *reinterpret_cast<__nv_bfloat162*>(&uv.x);
            __nv_bfloat162 vb1 = *reinterpret_cast<__nv_bfloat162*>(&uv.y);
            float2 v0 = __bfloat1622float2(vb0), v1 = __bfloat1622float2(vb1);

            float mn = fmaxf(m, p);
            float c = __expf(m - mn);   // first edge: exp(-inf)=0
            float w = __expf(p - mn);
            ssum = ssum * c + w;
            a0 = a0 * c + w * v0.x;
            a1 = a1 * c + w * v0.y;
            a2 = a2 * c + w * v1.x;
            a3 = a3 * c + w * v1.y;
            m = mn;
        }
    }

    float inv = (ssum > 0.f) ? (1.f / ssum) : 0.f;
    float4 fr = *reinterpret_cast<const float4*>(&feat[(long)node * 128 + lane * 4]);
    float x0 = a0 * inv + fr.x;
    float x1 = a1 * inv + fr.y;
    float x2 = a2 * inv + fr.z;
    float x3 = a3 * inv + fr.w;

    float part = x0 + x1 + x2 + x3;
#pragma unroll
    for (int o = 16; o >= 1; o >>= 1) part += __shfl_xor_sync(0xffffffffu, part, o);
    float mu = part * (1.f / 128.f);
    float d0 = x0 - mu, d1 = x1 - mu, d2 = x2 - mu, d3 = x3 - mu;
    float vp = d0 * d0 + d1 * d1 + d2 * d2 + d3 * d3;
#pragma unroll
    for (int o = 16; o >= 1; o >>= 1) vp += __shfl_xor_sync(0xffffffffu, vp, o);
    float rstd = rsqrtf(vp * (1.f / 128.f) + 1e-5f);

    float4 gg = *reinterpret_cast<const float4*>(&ln1g[lane * 4]);
    float4 bb = *reinterpret_cast<const float4*>(&ln1b[lane * 4]);
    float y0 = d0 * rstd * gg.x + bb.x;
    float y1 = d1 * rstd * gg.y + bb.y;
    float y2 = d2 * rstd * gg.z + bb.z;
    float y3 = d3 * rstd * gg.w + bb.w;

    float4 o4 = make_float4(y0, y1, y2, y3);
    *reinterpret_cast<float4*>(&g_rst[(long)node * 128 + lane * 4]) = o4;
    __nv_bfloat162 p0, p1;
    p0.x = __float2bfloat16_rn(y0); p0.y = __float2bfloat16_rn(y1);
    p1.x = __float2bfloat16_rn(y2); p1.y = __float2bfloat16_rn(y3);
    uint2 pk;
    pk.x = *reinterpret_cast<unsigned*>(&p0);
    pk.y = *reinterpret_cast<unsigned*>(&p1);
    *reinterpret_cast<uint2*>(&g_rstbf[(long)node * 128 + lane * 4]) = pk;
}

// ---------------- residual + LayerNorm2 -> output (warp per node) ----------------
__global__ __launch_bounds__(256) void k_ln2(
    const float* __restrict__ ln2g, const float* __restrict__ ln2b,
    float* __restrict__ out, int N)
{
    int gw = (blockIdx.x * blockDim.x + threadIdx.x) >> 5;
    if (gw >= N) return;
    int lane = threadIdx.x & 31;

    float4 r4 = *reinterpret_cast<const float4*>(&g_rst[(long)gw * 128 + lane * 4]);
    float4 f4 = *reinterpret_cast<const float4*>(&g_ffn[(long)gw * 128 + lane * 4]);
    float x0 = r4.x + f4.x, x1 = r4.y + f4.y, x2 = r4.z + f4.z, x3 = r4.w + f4.w;

    float part = x0 + x1 + x2 + x3;
#pragma unroll
    for (int o = 16; o >= 1; o >>= 1) part += __shfl_xor_sync(0xffffffffu, part, o);
    float mu = part * (1.f / 128.f);
    float d0 = x0 - mu, d1 = x1 - mu, d2 = x2 - mu, d3 = x3 - mu;
    float vp = d0 * d0 + d1 * d1 + d2 * d2 + d3 * d3;
#pragma unroll
    for (int o = 16; o >= 1; o >>= 1) vp += __shfl_xor_sync(0xffffffffu, vp, o);
    float rstd = rsqrtf(vp * (1.f / 128.f) + 1e-5f);

    float4 gg = *reinterpret_cast<const float4*>(&ln2g[lane * 4]);
    float4 bb = *reinterpret_cast<const float4*>(&ln2b[lane * 4]);
    float4 o4;
    o4.x = d0 * rstd * gg.x + bb.x;
    o4.y = d1 * rstd * gg.y + bb.y;
    o4.z = d2 * rstd * gg.z + bb.z;
    o4.w = d3 * rstd * gg.w + bb.w;
    *reinterpret_cast<float4*>(&out[(long)gw * 128 + lane * 4]) = o4;
}

// ---------------- launch ----------------
extern "C" void kernel_launch(void* const* d_in, const int* in_sizes, int n_in,
                              void* d_out, int out_size)
{
    const float* feat  = (const float*)d_in[0];
    const int*   src   = (const int*)d_in[1];
    const int*   dst   = (const int*)d_in[2];
    const float* Wq    = (const float*)d_in[3];
    const float* Wk    = (const float*)d_in[4];
    const float* Wv    = (const float*)d_in[5];
    const float* ln1g  = (const float*)d_in[6];
    const float* ln1b  = (const float*)d_in[7];
    const float* ln2g  = (const float*)d_in[8];
    const float* ln2b  = (const float*)d_in[9];
    const float* W1    = (const float*)d_in[10];
    const float* b1    = (const float*)d_in[11];
    const float* prelu = (const float*)d_in[12];
    const float* W2    = (const float*)d_in[13];
    const float* b2    = (const float*)d_in[14];
    float* out = (float*)d_out;

    int N = in_sizes[0] / 128;
    int E = in_sizes[1];

    void *degp, *curp;
    cudaGetSymbolAddress(&degp, g_deg);
    cudaGetSymbolAddress(&curp, g_cursor);
    cudaMemsetAsync(degp, 0, (size_t)N * 4);
    cudaMemsetAsync(curp, 0, (size_t)N * 4);

    // converts
    k_cvt_feat<<<(N * 128 / 4 + 255) / 256, 256>>>(feat, N * 128);
    dim3 gw(64, 5);
    k_cvt_w<<<gw, 256>>>(Wq, Wk, Wv, W1, W2);

    // CSR build
    k_hist<<<(E + 255) / 256, 256>>>(dst, E);
    int nb = (N + 255) / 256;
    k_scan1<<<nb, 256>>>(N);
    k_scan2<<<1, 256>>>(nb);
    k_scan3<<<nb, 256>>>(N);
    k_fill<<<(E + 255) / 256, 256>>>(dst, src, E);

    int mblk = (N + 127) / 128;

    // QKV (bf16 tensor cores)
    dim3 gqkv(3, mblk);
    gemm_qkv<<<gqkv, 256>>>(N);

    // attention + aggregate + residual + LN1 (warp per node)
    k_attn<<<(N * 32 + 255) / 256, 256>>>(feat, ln1g, ln1b, N);

    // FFN
    dim3 gff1(4, mblk);
    gemm_ffn1<<<gff1, 256>>>(N, b1, prelu);
    dim3 gff2(1, mblk);
    gemm_ffn2<<<gff2, 256>>>(N, b2);

    // residual + LN2 -> out (warp per node)
    k_ln2<<<(N * 32 + 255) / 256, 256>>>(ln2g, ln2b, out, N);
}